// round 9
// baseline (speedup 1.0000x reference)
#include <cuda_runtime.h>
#include <cuda_fp16.h>

#define NN 100000
#define NE 1000000
#define NB1 98                // ceil(NN/1024)

// ---------------- scratch (static device globals; no allocation) ----------------
__device__ __half g_xh[NN * 32];     // x in fp16, rows padded to 32 (64B aligned)
__device__ __half g_fh[NN * 64];     // layer1 output in fp16 (128B rows)
__device__ float  g_as[NN], g_ad[NN];    // layer1 logit projections
__device__ float  g_as2[NN], g_ad2[NN];  // layer2 logit projections
__device__ int    g_cnt[NN];
__device__ int    g_rowptr[NN + 1];
__device__ int    g_cursor[NN];
__device__ float2 g_ew1[NE];         // per CSR slot: (src as int-bits, exp weight L1)
__device__ float2 g_ew2[NE];         // per CSR slot: (src as int-bits, exp weight L2)
__device__ int    g_dst[NE];         // dst per CSR slot (for k_wgt2)
__device__ int    g_bsum[128], g_boff[128];
__device__ int    g_is64;
__device__ float  g_va1[20], g_vd1[20];
__device__ float  g_va2[64], g_vd2[64];
__device__ float  g_csum[64 * 32];   // padded column sums (128B stride)

__device__ __forceinline__ float lrelu(float e) { return (e > 0.f) ? e : 0.2f * e; }

// ---------------- init: cnt=0, csum=0, dtype detect, attention-vector projections ----
__global__ void k_init(const int* __restrict__ e,
                       const float* __restrict__ W1, const float* __restrict__ as1,
                       const float* __restrict__ ad1,
                       const float* __restrict__ W2, const float* __restrict__ as2,
                       const float* __restrict__ ad2) {
    int i = blockIdx.x * blockDim.x + threadIdx.x;
    if (i < NN) g_cnt[i] = 0;
    if (i < 64 * 32) g_csum[i] = 0.f;
    if (blockIdx.x == 0) {
        int t = threadIdx.x;
        if (t == 0) {
            int allz = 1;                       // int64: odd words are zero high halves
            for (int j = 1; j < 64; j += 2)
                if (e[j] != 0) allz = 0;
            g_is64 = allz;
        }
        if (t < 64) {
            float s = 0.f;
            for (int c = 0; c < 64; c++) s += W2[t * 64 + c] * as2[c];
            g_va2[t] = s;
        } else if (t < 128) {
            int k = t - 64; float s = 0.f;
            for (int c = 0; c < 64; c++) s += W2[k * 64 + c] * ad2[c];
            g_vd2[k] = s;
        } else if (t < 148) {
            int k = t - 128; float s = 0.f;
            for (int c = 0; c < 64; c++) s += W1[k * 64 + c] * as1[c];
            g_va1[k] = s;
        } else if (t < 168) {
            int k = t - 148; float s = 0.f;
            for (int c = 0; c < 64; c++) s += W1[k * 64 + c] * ad1[c];
            g_vd1[k] = s;
        }
    }
}

// ---------------- prep: x -> half (padded rows), layer1 logit projections ----------
__global__ void __launch_bounds__(256)
k_prep1(const float* __restrict__ x) {
    int n = blockIdx.x * blockDim.x + threadIdx.x;
    if (n >= NN) return;
    const float4* r4 = (const float4*)(x + (size_t)n * 20);
    float v[20];
    #pragma unroll
    for (int q = 0; q < 5; q++) {
        float4 t = r4[q];
        v[4 * q] = t.x; v[4 * q + 1] = t.y; v[4 * q + 2] = t.z; v[4 * q + 3] = t.w;
    }
    float ps = 0.f, pd = 0.f;
    __half2* xo = (__half2*)(g_xh + (size_t)n * 32);
    #pragma unroll
    for (int k = 0; k < 20; k += 2) {
        ps += v[k] * g_va1[k] + v[k + 1] * g_va1[k + 1];
        pd += v[k] * g_vd1[k] + v[k + 1] * g_vd1[k + 1];
        xo[k >> 1] = __floats2half2_rn(v[k], v[k + 1]);
    }
    g_as[n] = ps; g_ad[n] = pd;
}

// ---------------- CSR build (in-edges only; self-loops inline in agg) --------------
__global__ void k_hist(const void* __restrict__ ei) {
    int q = blockIdx.x * blockDim.x + threadIdx.x;   // quad of edges
    if (q >= NE / 4) return;
    int d0, d1, d2, d3;
    if (g_is64) {
        const longlong2* p = (const longlong2*)((const long long*)ei + NE);
        longlong2 a = p[2 * q], b = p[2 * q + 1];
        d0 = (int)a.x; d1 = (int)a.y; d2 = (int)b.x; d3 = (int)b.y;
    } else {
        int4 d = ((const int4*)((const int*)ei + NE))[q];
        d0 = d.x; d1 = d.y; d2 = d.z; d3 = d.w;
    }
    if ((unsigned)d0 < NN) atomicAdd(&g_cnt[d0], 1);
    if ((unsigned)d1 < NN) atomicAdd(&g_cnt[d1], 1);
    if ((unsigned)d2 < NN) atomicAdd(&g_cnt[d2], 1);
    if ((unsigned)d3 < NN) atomicAdd(&g_cnt[d3], 1);
}

__global__ void k_scan1() {
    __shared__ int wsum[32];
    int t = threadIdx.x;
    int idx = blockIdx.x * 1024 + t;
    int v = (idx < NN) ? g_cnt[idx] : 0;
    int x = v;
    for (int o = 1; o < 32; o <<= 1) {
        int u = __shfl_up_sync(0xffffffffu, x, o);
        if ((t & 31) >= o) x += u;
    }
    if ((t & 31) == 31) wsum[t >> 5] = x;
    __syncthreads();
    if (t < 32) {
        int y = wsum[t];
        for (int o = 1; o < 32; o <<= 1) {
            int u = __shfl_up_sync(0xffffffffu, y, o);
            if (t >= o) y += u;
        }
        wsum[t] = y;
    }
    __syncthreads();
    int base = (t >= 32) ? wsum[(t >> 5) - 1] : 0;
    int incl = x + base;
    if (idx < NN) g_rowptr[idx] = incl - v;
    if (t == 1023) g_bsum[blockIdx.x] = incl;
}

__global__ void k_scan2(int nb) {
    __shared__ int s[128];
    int t = threadIdx.x;
    int v = (t < nb) ? g_bsum[t] : 0;
    s[t] = v;
    __syncthreads();
    for (int o = 1; o < 128; o <<= 1) {
        int u = (t >= o) ? s[t - o] : 0;
        __syncthreads();
        s[t] += u;
        __syncthreads();
    }
    g_boff[t] = s[t] - v;
}

__global__ void k_scan3() {
    int t = threadIdx.x;
    int idx = blockIdx.x * 1024 + t;
    if (idx < NN) {
        int r = g_rowptr[idx] + g_boff[blockIdx.x];
        g_rowptr[idx] = r;
        g_cursor[idx] = r;
    }
    if (idx == 0) g_rowptr[NN] = NE;
}

// ---------------- scatter + fused layer-1 edge weights ----------------
__global__ void k_scatter(const void* __restrict__ ei) {
    int q = blockIdx.x * blockDim.x + threadIdx.x;
    if (q >= NE / 4) return;
    int s[4], d[4];
    if (g_is64) {
        const longlong2* ps = (const longlong2*)ei;
        const longlong2* pd = (const longlong2*)((const long long*)ei + NE);
        longlong2 a = ps[2 * q], b = ps[2 * q + 1];
        longlong2 c = pd[2 * q], e = pd[2 * q + 1];
        s[0] = (int)a.x; s[1] = (int)a.y; s[2] = (int)b.x; s[3] = (int)b.y;
        d[0] = (int)c.x; d[1] = (int)c.y; d[2] = (int)e.x; d[3] = (int)e.y;
    } else {
        int4 a = ((const int4*)ei)[q];
        int4 e = ((const int4*)((const int*)ei + NE))[q];
        s[0] = a.x; s[1] = a.y; s[2] = a.z; s[3] = a.w;
        d[0] = e.x; d[1] = e.y; d[2] = e.z; d[3] = e.w;
    }
    #pragma unroll
    for (int i = 0; i < 4; i++) {
        if ((unsigned)d[i] < NN && (unsigned)s[i] < NN) {
            float wg = __expf(lrelu(g_as[s[i]] + g_ad[d[i]]));
            int p = atomicAdd(&g_cursor[d[i]], 1);
            g_ew1[p] = make_float2(__int_as_float(s[i]), wg);
            g_dst[p] = d[i];
        }
    }
}

// ---------------- layer-2 edge weights (edge-parallel, full MLP) ----------------
__global__ void __launch_bounds__(256)
k_wgt2() {
    int p = blockIdx.x * blockDim.x + threadIdx.x;
    if (p >= NE) return;
    float2 e = g_ew1[p];
    int s = __float_as_int(e.x);
    int d = g_dst[p];
    float wg = __expf(lrelu(g_as2[s] + g_ad2[d]));
    g_ew2[p] = make_float2(e.x, wg);
}

// ---------------- layer 1: softmax-agg x (fp16), fused W1 GEMV, fused proj2 --------
__global__ void __launch_bounds__(256)
k_agg1(const float* __restrict__ W1, const float* __restrict__ b1) {
    __shared__ float s_W1[20 * 64];
    for (int i = threadIdx.x; i < 20 * 64; i += 256) s_W1[i] = W1[i];
    __syncthreads();

    int w = (blockIdx.x * 256 + threadIdx.x) >> 5;    // grid exact: NN/8 warps
    int lane = threadIdx.x & 31;
    int start = g_rowptr[w];
    int deg = g_rowptr[w + 1] - start;
    const float2* ew = g_ew1 + start;

    // self-loop weight (warp-uniform)
    float swg = __expf(lrelu(g_as[w] + g_ad[w]));

    // phase A: coalesced denominator
    float denom = (lane == 0) ? swg : 0.f;
    for (int j = lane; j < deg; j += 32) denom += ew[j].y;
    for (int o = 16; o; o >>= 1) denom += __shfl_xor_sync(0xffffffffu, denom, o);

    // phase B: uniform edge loop, unroll 4; lanes 0..19 gather padded x rows
    const __half* xh = g_xh;
    float acc = (lane < 20) ? swg * __half2float(xh[(size_t)w * 32 + lane]) : 0.f;
    int j = 0;
    for (; j + 4 <= deg; j += 4) {
        float2 e0 = ew[j], e1 = ew[j + 1], e2 = ew[j + 2], e3 = ew[j + 3];
        if (lane < 20) {
            float h0 = __half2float(xh[(size_t)__float_as_int(e0.x) * 32 + lane]);
            float h1 = __half2float(xh[(size_t)__float_as_int(e1.x) * 32 + lane]);
            float h2 = __half2float(xh[(size_t)__float_as_int(e2.x) * 32 + lane]);
            float h3 = __half2float(xh[(size_t)__float_as_int(e3.x) * 32 + lane]);
            acc += e0.y * h0 + e1.y * h1 + e2.y * h2 + e3.y * h3;
        }
    }
    for (; j < deg; j++) {
        float2 e0 = ew[j];
        if (lane < 20) acc += e0.y * __half2float(xh[(size_t)__float_as_int(e0.x) * 32 + lane]);
    }
    acc *= (1.f / denom);

    // fused GEMV: out[c] = sum_k acc_k * W1[k][c]; lane owns cols 2l, 2l+1
    float o0 = 0.f, o1 = 0.f;
    #pragma unroll
    for (int k = 0; k < 20; k++) {
        float xk = __shfl_sync(0xffffffffu, acc, k);
        float2 wv = ((const float2*)(s_W1 + k * 64))[lane];
        o0 += xk * wv.x;
        o1 += xk * wv.y;
    }
    float2 bv = ((const float2*)b1)[lane];
    o0 = fmaxf(o0 + bv.x, 0.f);
    o1 = fmaxf(o1 + bv.y, 0.f);
    ((__half2*)g_fh)[(size_t)w * 32 + lane] = __floats2half2_rn(o0, o1);

    // fused layer-2 logit projections (fp32 pre-rounding values)
    float2 va = ((const float2*)g_va2)[lane];
    float2 vd = ((const float2*)g_vd2)[lane];
    float ps = o0 * va.x + o1 * va.y;
    float pd = o0 * vd.x + o1 * vd.y;
    for (int o = 16; o; o >>= 1) {
        ps += __shfl_xor_sync(0xffffffffu, ps, o);
        pd += __shfl_xor_sync(0xffffffffu, pd, o);
    }
    if (lane == 0) { g_as2[w] = ps; g_ad2[w] = pd; }
}

// ---------------- layer 2: softmax-agg feat (fp16) + fused mean (persistent) -------
__global__ void __launch_bounds__(256)
k_agg2() {
    __shared__ float s_red[8][64];
    int lane = threadIdx.x & 31;
    int wl = threadIdx.x >> 5;
    int gw = (blockIdx.x * 256 + threadIdx.x) >> 5;
    int nwarps = gridDim.x * 8;
    const __half2* fh = (const __half2*)g_fh;

    float tx = 0.f, ty = 0.f;            // persistent column totals (cols 2l, 2l+1)
    for (int w = gw; w < NN; w += nwarps) {
        int start = g_rowptr[w];
        int deg = g_rowptr[w + 1] - start;
        const float2* ew = g_ew2 + start;

        float swg = __expf(lrelu(g_as2[w] + g_ad2[w]));

        float denom = (lane == 0) ? swg : 0.f;
        for (int j = lane; j < deg; j += 32) denom += ew[j].y;
        for (int o = 16; o; o >>= 1) denom += __shfl_xor_sync(0xffffffffu, denom, o);

        float2 hs = __half22float2(fh[(size_t)w * 32 + lane]);
        float ax = swg * hs.x, ay = swg * hs.y;
        int j = 0;
        for (; j + 4 <= deg; j += 4) {
            float2 e0 = ew[j], e1 = ew[j + 1], e2 = ew[j + 2], e3 = ew[j + 3];
            float2 h0 = __half22float2(fh[(size_t)__float_as_int(e0.x) * 32 + lane]);
            float2 h1 = __half22float2(fh[(size_t)__float_as_int(e1.x) * 32 + lane]);
            float2 h2 = __half22float2(fh[(size_t)__float_as_int(e2.x) * 32 + lane]);
            float2 h3 = __half22float2(fh[(size_t)__float_as_int(e3.x) * 32 + lane]);
            ax += e0.y * h0.x + e1.y * h1.x + e2.y * h2.x + e3.y * h3.x;
            ay += e0.y * h0.y + e1.y * h1.y + e2.y * h2.y + e3.y * h3.y;
        }
        for (; j < deg; j++) {
            float2 e0 = ew[j];
            float2 h0 = __half22float2(fh[(size_t)__float_as_int(e0.x) * 32 + lane]);
            ax += e0.y * h0.x;
            ay += e0.y * h0.y;
        }
        float inv = 1.f / denom;
        tx += ax * inv;
        ty += ay * inv;
    }
    s_red[wl][2 * lane] = tx;
    s_red[wl][2 * lane + 1] = ty;
    __syncthreads();
    if (threadIdx.x < 64) {
        float t = 0.f;
        #pragma unroll
        for (int i = 0; i < 8; i++) t += s_red[i][threadIdx.x];
        atomicAdd(&g_csum[threadIdx.x * 32], t);   // 128B stride -> spread LTS partitions
    }
}

// ---------------- final: out = (colmean) @ W2 + b2 ----------------
__global__ void k_final(const float* __restrict__ W2, const float* __restrict__ b2,
                        float* __restrict__ out) {
    __shared__ float m[64];
    int t = threadIdx.x;
    if (t < 64) m[t] = g_csum[t * 32] * (1.0f / NN);
    __syncthreads();
    if (t < 64) {
        float s = b2[t];
        for (int k = 0; k < 64; k++) s += m[k] * W2[k * 64 + t];
        out[t] = s;
    }
}

// ---------------- launch ----------------
extern "C" void kernel_launch(void* const* d_in, const int* in_sizes, int n_in,
                              void* d_out, int out_size) {
    const float* x   = (const float*)d_in[0];
    const void*  ei  = d_in[1];
    const float* W1  = (const float*)d_in[2];
    const float* as1 = (const float*)d_in[3];
    const float* ad1 = (const float*)d_in[4];
    const float* b1  = (const float*)d_in[5];
    const float* W2  = (const float*)d_in[6];
    const float* as2 = (const float*)d_in[7];
    const float* ad2 = (const float*)d_in[8];
    const float* b2  = (const float*)d_in[9];
    float* out = (float*)d_out;

    int gN = (NN + 255) / 256;           // 391
    int gQ = (NE / 4 + 255) / 256;       // 977 (quad-edge kernels)
    int gE = (NE + 255) / 256;           // 3907
    int gW = NN / 8;                     // 12500 (warp-per-node)

    k_init<<<gN, 256>>>((const int*)ei, W1, as1, ad1, W2, as2, ad2);
    k_prep1<<<gN, 256>>>(x);
    k_hist<<<gQ, 256>>>(ei);
    k_scan1<<<NB1, 1024>>>();
    k_scan2<<<1, 128>>>(NB1);
    k_scan3<<<NB1, 1024>>>();
    k_scatter<<<gQ, 256>>>(ei);

    k_agg1<<<gW, 256>>>(W1, b1);
    k_wgt2<<<gE, 256>>>();
    k_agg2<<<1184, 256>>>();             // persistent: 148 SMs x 8 blocks
    k_final<<<1, 64>>>(W2, b2, out);
}

// round 10
// speedup vs baseline: 1.0398x; 1.0398x over previous
#include <cuda_runtime.h>
#include <cuda_fp16.h>

#define NN 100000
#define NE 1000000
#define NB1 98                // ceil(NN/1024)
#define CAP 96                // smem-staged edges per node (max degree ~35 here)
#define AGG2_GRID 1184        // persistent: 148 SMs x 8 blocks

// ---------------- scratch (static device globals; no allocation) ----------------
__device__ __half g_xh[NN * 32];     // x in fp16, rows padded to 32 halves (64B)
__device__ __half g_fh[NN * 64];     // layer1 output in fp16 (128B rows)
__device__ float  g_as[NN], g_ad[NN];    // layer1 logit projections
__device__ float  g_as2[NN], g_ad2[NN];  // layer2 logit projections
__device__ int    g_cnt[NN];
__device__ int    g_rowptr[NN + 1];
__device__ int    g_cursor[NN];
__device__ int    g_col[NE];         // src per CSR slot (self-loops inline in agg)
__device__ int    g_bsum[128];
__device__ int    g_is64;
__device__ int    g_done;
__device__ float  g_va2[64], g_vd2[64];  // W2 @ a_src2 / a_dst2
__device__ float  g_csum[64 * 32];       // padded column sums (128B stride)

__device__ __forceinline__ float lrelu(float e) { return (e > 0.f) ? e : 0.2f * e; }

// ---------------- fused init + prep1 ----------------
// All blocks: zero cnt/csum/done slices; per-block va1/vd1 (tiny, recomputed);
// then thread-per-node: x -> half (padded), layer1 logit projections.
// Block 0 additionally: dtype detect + va2/vd2 (needed first by k_agg1, much later).
__global__ void __launch_bounds__(256)
k_init_prep(const float* __restrict__ x, const int* __restrict__ e,
            const float* __restrict__ W1, const float* __restrict__ as1,
            const float* __restrict__ ad1,
            const float* __restrict__ W2, const float* __restrict__ as2,
            const float* __restrict__ ad2) {
    __shared__ float s_va1[20], s_vd1[20];
    int t = threadIdx.x;
    int n = blockIdx.x * 256 + t;
    if (n < NN) g_cnt[n] = 0;
    if (n < 64 * 32) g_csum[n] = 0.f;
    if (n == 0) g_done = 0;
    if (t < 20) {
        float s = 0.f;
        for (int c = 0; c < 64; c++) s += W1[t * 64 + c] * as1[c];
        s_va1[t] = s;
    } else if (t < 40) {
        int k = t - 20; float s = 0.f;
        for (int c = 0; c < 64; c++) s += W1[k * 64 + c] * ad1[c];
        s_vd1[k] = s;
    }
    if (blockIdx.x == 0) {
        if (t == 64) {
            int allz = 1;                    // int64: odd words are zero high halves
            for (int j = 1; j < 64; j += 2)
                if (e[j] != 0) allz = 0;
            g_is64 = allz;
        }
        if (t >= 128 && t < 192) {
            int k = t - 128; float s = 0.f;
            for (int c = 0; c < 64; c++) s += W2[k * 64 + c] * as2[c];
            g_va2[k] = s;
        } else if (t >= 192) {
            int k = t - 192; float s = 0.f;
            for (int c = 0; c < 64; c++) s += W2[k * 64 + c] * ad2[c];
            g_vd2[k] = s;
        }
    }
    __syncthreads();
    if (n >= NN) return;
    const float4* r4 = (const float4*)(x + (size_t)n * 20);
    float v[20];
    #pragma unroll
    for (int q = 0; q < 5; q++) {
        float4 tv = r4[q];
        v[4 * q] = tv.x; v[4 * q + 1] = tv.y; v[4 * q + 2] = tv.z; v[4 * q + 3] = tv.w;
    }
    float ps = 0.f, pd = 0.f;
    __half2* xo = (__half2*)(g_xh + (size_t)n * 32);
    #pragma unroll
    for (int k = 0; k < 20; k += 2) {
        ps += v[k] * s_va1[k] + v[k + 1] * s_va1[k + 1];
        pd += v[k] * s_vd1[k] + v[k + 1] * s_vd1[k + 1];
        xo[k >> 1] = __floats2half2_rn(v[k], v[k + 1]);
    }
    g_as[n] = ps; g_ad[n] = pd;
}

// ---------------- CSR build (in-edges only) ----------------
__global__ void k_hist(const void* __restrict__ ei) {
    int q = blockIdx.x * blockDim.x + threadIdx.x;   // quad of edges
    if (q >= NE / 4) return;
    int d0, d1, d2, d3;
    if (g_is64) {
        const longlong2* p = (const longlong2*)((const long long*)ei + NE);
        longlong2 a = p[2 * q], b = p[2 * q + 1];
        d0 = (int)a.x; d1 = (int)a.y; d2 = (int)b.x; d3 = (int)b.y;
    } else {
        int4 d = ((const int4*)((const int*)ei + NE))[q];
        d0 = d.x; d1 = d.y; d2 = d.z; d3 = d.w;
    }
    if ((unsigned)d0 < NN) atomicAdd(&g_cnt[d0], 1);
    if ((unsigned)d1 < NN) atomicAdd(&g_cnt[d1], 1);
    if ((unsigned)d2 < NN) atomicAdd(&g_cnt[d2], 1);
    if ((unsigned)d3 < NN) atomicAdd(&g_cnt[d3], 1);
}

__global__ void k_scan1() {
    __shared__ int wsum[32];
    int t = threadIdx.x;
    int idx = blockIdx.x * 1024 + t;
    int v = (idx < NN) ? g_cnt[idx] : 0;
    int x = v;
    for (int o = 1; o < 32; o <<= 1) {
        int u = __shfl_up_sync(0xffffffffu, x, o);
        if ((t & 31) >= o) x += u;
    }
    if ((t & 31) == 31) wsum[t >> 5] = x;
    __syncthreads();
    if (t < 32) {
        int y = wsum[t];
        for (int o = 1; o < 32; o <<= 1) {
            int u = __shfl_up_sync(0xffffffffu, y, o);
            if (t >= o) y += u;
        }
        wsum[t] = y;
    }
    __syncthreads();
    int base = (t >= 32) ? wsum[(t >> 5) - 1] : 0;
    int incl = x + base;
    if (idx < NN) g_rowptr[idx] = incl - v;
    if (t == 1023) g_bsum[blockIdx.x] = incl;
}

// fused scan2+scan3: each block redundantly sums bsum[0..bid) (<=4 warp iters)
__global__ void k_scan23() {
    __shared__ int s_boff;
    int t = threadIdx.x, bid = blockIdx.x;
    if (t < 32) {
        int s = 0;
        for (int i = t; i < bid; i += 32) s += g_bsum[i];
        for (int o = 16; o; o >>= 1) s += __shfl_xor_sync(0xffffffffu, s, o);
        if (t == 0) s_boff = s;
    }
    __syncthreads();
    int idx = bid * 1024 + t;
    if (idx < NN) {
        int r = g_rowptr[idx] + s_boff;
        g_rowptr[idx] = r;
        g_cursor[idx] = r;
    }
    if (idx == 0) g_rowptr[NN] = NE;
}

__global__ void k_scatter(const void* __restrict__ ei) {
    int q = blockIdx.x * blockDim.x + threadIdx.x;
    if (q >= NE / 4) return;
    int s0, s1, s2, s3, d0, d1, d2, d3;
    if (g_is64) {
        const longlong2* ps = (const longlong2*)ei;
        const longlong2* pd = (const longlong2*)((const long long*)ei + NE);
        longlong2 a = ps[2 * q], b = ps[2 * q + 1];
        longlong2 c = pd[2 * q], d = pd[2 * q + 1];
        s0 = (int)a.x; s1 = (int)a.y; s2 = (int)b.x; s3 = (int)b.y;
        d0 = (int)c.x; d1 = (int)c.y; d2 = (int)d.x; d3 = (int)d.y;
    } else {
        int4 a = ((const int4*)ei)[q];
        int4 d = ((const int4*)((const int*)ei + NE))[q];
        s0 = a.x; s1 = a.y; s2 = a.z; s3 = a.w;
        d0 = d.x; d1 = d.y; d2 = d.z; d3 = d.w;
    }
    if ((unsigned)d0 < NN && (unsigned)s0 < NN) g_col[atomicAdd(&g_cursor[d0], 1)] = s0;
    if ((unsigned)d1 < NN && (unsigned)s1 < NN) g_col[atomicAdd(&g_cursor[d1], 1)] = s1;
    if ((unsigned)d2 < NN && (unsigned)s2 < NN) g_col[atomicAdd(&g_cursor[d2], 1)] = s2;
    if ((unsigned)d3 < NN && (unsigned)s3 < NN) g_col[atomicAdd(&g_cursor[d3], 1)] = s3;
}

// ---------------- layer 1: softmax-agg x (fp16), fused W1 GEMV, fused proj2 --------
__global__ void __launch_bounds__(256)
k_agg1(const float* __restrict__ W1, const float* __restrict__ b1) {
    __shared__ float  s_W1[20 * 64];
    __shared__ float2 s_ew[8][CAP];      // (src as int-bits, exp weight)
    for (int i = threadIdx.x; i < 20 * 64; i += 256) s_W1[i] = W1[i];
    __syncthreads();

    int w = (blockIdx.x * 256 + threadIdx.x) >> 5;    // grid exact: NN/8 warps
    int lane = threadIdx.x & 31;
    int wl = threadIdx.x >> 5;
    int start = g_rowptr[w];
    int deg = g_rowptr[w + 1] - start;
    float adi = g_ad[w];
    int nm = deg < CAP ? deg : CAP;

    // self loop (warp-uniform)
    float swg = __expf(lrelu(g_as[w] + adi));

    // phase A: lane-parallel weights into smem + denominator
    float denom = (lane == 0) ? swg : 0.f;
    for (int j = lane; j < nm; j += 32) {
        int s = g_col[start + j];
        float wg = __expf(lrelu(g_as[s] + adi));
        s_ew[wl][j] = make_float2(__int_as_float(s), wg);
        denom += wg;
    }
    for (int o = 16; o; o >>= 1) denom += __shfl_xor_sync(0xffffffffu, denom, o);
    __syncwarp();

    // phase B: uniform edge loop, unroll 4; lanes 0..19 gather padded x rows
    const __half* xh = g_xh;
    float acc = (lane < 20) ? swg * __half2float(xh[(size_t)w * 32 + lane]) : 0.f;
    int j = 0;
    for (; j + 4 <= nm; j += 4) {
        float2 e0 = s_ew[wl][j],     e1 = s_ew[wl][j + 1];
        float2 e2 = s_ew[wl][j + 2], e3 = s_ew[wl][j + 3];
        if (lane < 20) {
            float h0 = __half2float(xh[(size_t)__float_as_int(e0.x) * 32 + lane]);
            float h1 = __half2float(xh[(size_t)__float_as_int(e1.x) * 32 + lane]);
            float h2 = __half2float(xh[(size_t)__float_as_int(e2.x) * 32 + lane]);
            float h3 = __half2float(xh[(size_t)__float_as_int(e3.x) * 32 + lane]);
            acc += e0.y * h0 + e1.y * h1 + e2.y * h2 + e3.y * h3;
        }
    }
    for (; j < nm; j++) {
        float2 e0 = s_ew[wl][j];
        if (lane < 20) acc += e0.y * __half2float(xh[(size_t)__float_as_int(e0.x) * 32 + lane]);
    }
    for (j = CAP; j < deg; j++) {        // overflow path (not hit at this degree dist)
        int s = g_col[start + j];
        float wg = __expf(lrelu(g_as[s] + adi));
        denom += wg;                     // uniform across warp: consistent
        if (lane < 20) acc += wg * __half2float(xh[(size_t)s * 32 + lane]);
    }
    acc *= (1.f / denom);

    // fused GEMV: out[c] = sum_k acc_k * W1[k][c]; lane owns cols 2l, 2l+1
    float o0 = 0.f, o1 = 0.f;
    #pragma unroll
    for (int k = 0; k < 20; k++) {
        float xk = __shfl_sync(0xffffffffu, acc, k);
        float2 wv = ((const float2*)(s_W1 + k * 64))[lane];
        o0 += xk * wv.x;
        o1 += xk * wv.y;
    }
    float2 bv = ((const float2*)b1)[lane];
    o0 = fmaxf(o0 + bv.x, 0.f);
    o1 = fmaxf(o1 + bv.y, 0.f);
    ((__half2*)g_fh)[(size_t)w * 32 + lane] = __floats2half2_rn(o0, o1);

    // fused layer-2 logit projections (fp32 pre-rounding values)
    float2 va = ((const float2*)g_va2)[lane];
    float2 vd = ((const float2*)g_vd2)[lane];
    float ps = o0 * va.x + o1 * va.y;
    float pd = o0 * vd.x + o1 * vd.y;
    for (int o = 16; o; o >>= 1) {
        ps += __shfl_xor_sync(0xffffffffu, ps, o);
        pd += __shfl_xor_sync(0xffffffffu, pd, o);
    }
    if (lane == 0) { g_as2[w] = ps; g_ad2[w] = pd; }
}

// ---------------- layer 2: softmax-agg feat (fp16) + fused mean + fused final -------
__global__ void __launch_bounds__(256)
k_agg2(const float* __restrict__ W2, const float* __restrict__ b2,
       float* __restrict__ out) {
    __shared__ float2 s_ew[8][CAP];
    __shared__ float  s_red[8][64];
    __shared__ int    s_last;
    int lane = threadIdx.x & 31;
    int wl = threadIdx.x >> 5;
    int gw = (blockIdx.x * 256 + threadIdx.x) >> 5;
    int nwarps = AGG2_GRID * 8;
    const __half2* fh = (const __half2*)g_fh;

    float tx = 0.f, ty = 0.f;            // persistent column totals (cols 2l, 2l+1)
    for (int w = gw; w < NN; w += nwarps) {
        int start = g_rowptr[w];
        int deg = g_rowptr[w + 1] - start;
        float adi = g_ad2[w];
        int nm = deg < CAP ? deg : CAP;

        float swg = __expf(lrelu(g_as2[w] + adi));

        float denom = (lane == 0) ? swg : 0.f;
        for (int j = lane; j < nm; j += 32) {
            int s = g_col[start + j];
            float wg = __expf(lrelu(g_as2[s] + adi));
            s_ew[wl][j] = make_float2(__int_as_float(s), wg);
            denom += wg;
        }
        for (int o = 16; o; o >>= 1) denom += __shfl_xor_sync(0xffffffffu, denom, o);
        __syncwarp();

        float2 hs = __half22float2(fh[(size_t)w * 32 + lane]);
        float ax = swg * hs.x, ay = swg * hs.y;
        int j = 0;
        for (; j + 4 <= nm; j += 4) {
            float2 e0 = s_ew[wl][j],     e1 = s_ew[wl][j + 1];
            float2 e2 = s_ew[wl][j + 2], e3 = s_ew[wl][j + 3];
            float2 h0 = __half22float2(fh[(size_t)__float_as_int(e0.x) * 32 + lane]);
            float2 h1 = __half22float2(fh[(size_t)__float_as_int(e1.x) * 32 + lane]);
            float2 h2 = __half22float2(fh[(size_t)__float_as_int(e2.x) * 32 + lane]);
            float2 h3 = __half22float2(fh[(size_t)__float_as_int(e3.x) * 32 + lane]);
            ax += e0.y * h0.x + e1.y * h1.x + e2.y * h2.x + e3.y * h3.x;
            ay += e0.y * h0.y + e1.y * h1.y + e2.y * h2.y + e3.y * h3.y;
        }
        for (; j < nm; j++) {
            float2 e0 = s_ew[wl][j];
            float2 h0 = __half22float2(fh[(size_t)__float_as_int(e0.x) * 32 + lane]);
            ax += e0.y * h0.x;
            ay += e0.y * h0.y;
        }
        for (j = CAP; j < deg; j++) {    // overflow path
            int s = g_col[start + j];
            float wg = __expf(lrelu(g_as2[s] + adi));
            denom += wg;
            float2 h0 = __half22float2(fh[(size_t)s * 32 + lane]);
            ax += wg * h0.x;
            ay += wg * h0.y;
        }
        float inv = 1.f / denom;
        tx += ax * inv;
        ty += ay * inv;
        __syncwarp();
    }
    s_red[wl][2 * lane] = tx;
    s_red[wl][2 * lane + 1] = ty;
    __syncthreads();
    if (threadIdx.x < 64) {
        float t = 0.f;
        #pragma unroll
        for (int i = 0; i < 8; i++) t += s_red[i][threadIdx.x];
        atomicAdd(&g_csum[threadIdx.x * 32], t);   // 128B stride -> spread LTS
        __threadfence();
    }
    __syncthreads();
    if (threadIdx.x == 0)
        s_last = (atomicAdd(&g_done, 1) == AGG2_GRID - 1);
    __syncthreads();
    if (s_last) {                        // last block: out = colmean @ W2 + b2
        __shared__ float m[64];
        int t = threadIdx.x;
        if (t < 64) m[t] = g_csum[t * 32] * (1.0f / NN);
        __syncthreads();
        if (t < 64) {
            float s = b2[t];
            for (int k = 0; k < 64; k++) s += m[k] * W2[k * 64 + t];
            out[t] = s;
        }
    }
}

// ---------------- launch ----------------
extern "C" void kernel_launch(void* const* d_in, const int* in_sizes, int n_in,
                              void* d_out, int out_size) {
    const float* x   = (const float*)d_in[0];
    const void*  ei  = d_in[1];
    const float* W1  = (const float*)d_in[2];
    const float* as1 = (const float*)d_in[3];
    const float* ad1 = (const float*)d_in[4];
    const float* b1  = (const float*)d_in[5];
    const float* W2  = (const float*)d_in[6];
    const float* as2 = (const float*)d_in[7];
    const float* ad2 = (const float*)d_in[8];
    const float* b2  = (const float*)d_in[9];
    float* out = (float*)d_out;

    int gN = (NN + 255) / 256;           // 391
    int gQ = (NE / 4 + 255) / 256;       // 977 (quad-edge kernels)
    int gW = NN / 8;                     // 12500 (warp-per-node)

    k_init_prep<<<gN, 256>>>(x, (const int*)ei, W1, as1, ad1, W2, as2, ad2);
    k_hist<<<gQ, 256>>>(ei);
    k_scan1<<<NB1, 1024>>>();
    k_scan23<<<NB1, 1024>>>();
    k_scatter<<<gQ, 256>>>(ei);

    k_agg1<<<gW, 256>>>(W1, b1);
    k_agg2<<<AGG2_GRID, 256>>>(W2, b2, out);
}

// round 12
// speedup vs baseline: 1.1103x; 1.0677x over previous
#include <cuda_runtime.h>
#include <cuda_fp16.h>

#define NN 100000
#define NE 1000000
#define SLOTS 64              // fixed bucket slots per node (Poisson(10): max deg ~30)
#define SPILLMAX 4096
#define AGG2_GRID 1184        // persistent: 148 SMs x 8 blocks

// ---------------- scratch (static device globals; no allocation) ----------------
__device__ __half g_xh[NN * 32];     // x in fp16, rows padded to 32 halves (64B)
__device__ __half g_fh[NN * 64];     // layer1 output in fp16 (128B rows)
__device__ float  g_as[NN], g_ad[NN];    // layer1 logit projections
__device__ float  g_as2[NN], g_ad2[NN];  // layer2 logit projections
__device__ int    g_cnt[NN];         // in-degree (bucket fill count)
__device__ int    g_slots[NN * SLOTS];   // src ids, bucketed by dst (256B rows)
__device__ int    g_spill_s[SPILLMAX], g_spill_d[SPILLMAX];
__device__ int    g_spillcnt;
__device__ int    g_is64;
__device__ int    g_done;
__device__ float  g_va2[64], g_vd2[64];  // W2 @ a_src2 / a_dst2
__device__ float  g_csum[64 * 32];       // padded column sums (128B stride)

__device__ __forceinline__ float lrelu(float e) { return (e > 0.f) ? e : 0.2f * e; }

// ---------------- fused init + prep ----------------
// All blocks: zero cnt/csum/flags slices; per-block va1/vd1 (tiny, recomputed);
// thread-per-node: x -> half (padded rows), layer1 logit projections.
// Block 0 additionally: dtype detect + va2/vd2 (first needed much later by k_agg1).
__global__ void __launch_bounds__(256)
k_init_prep(const float* __restrict__ x, const int* __restrict__ e,
            const float* __restrict__ W1, const float* __restrict__ as1,
            const float* __restrict__ ad1,
            const float* __restrict__ W2, const float* __restrict__ as2,
            const float* __restrict__ ad2) {
    __shared__ float s_va1[20], s_vd1[20];
    int t = threadIdx.x;
    int n = blockIdx.x * 256 + t;
    if (n < NN) g_cnt[n] = 0;
    if (n < 64 * 32) g_csum[n] = 0.f;
    if (n == 0) { g_done = 0; g_spillcnt = 0; }
    if (t < 20) {
        float s = 0.f;
        for (int c = 0; c < 64; c++) s += W1[t * 64 + c] * as1[c];
        s_va1[t] = s;
    } else if (t < 40) {
        int k = t - 20; float s = 0.f;
        for (int c = 0; c < 64; c++) s += W1[k * 64 + c] * ad1[c];
        s_vd1[k] = s;
    }
    if (blockIdx.x == 0) {
        if (t == 64) {
            int allz = 1;                    // int64: odd words are zero high halves
            for (int j = 1; j < 64; j += 2)
                if (e[j] != 0) allz = 0;
            g_is64 = allz;
        }
        if (t >= 128 && t < 192) {
            int k = t - 128; float s = 0.f;
            for (int c = 0; c < 64; c++) s += W2[k * 64 + c] * as2[c];
            g_va2[k] = s;
        } else if (t >= 192) {
            int k = t - 192; float s = 0.f;
            for (int c = 0; c < 64; c++) s += W2[k * 64 + c] * ad2[c];
            g_vd2[k] = s;
        }
    }
    __syncthreads();
    if (n >= NN) return;
    const float4* r4 = (const float4*)(x + (size_t)n * 20);
    float v[20];
    #pragma unroll
    for (int q = 0; q < 5; q++) {
        float4 tv = r4[q];
        v[4 * q] = tv.x; v[4 * q + 1] = tv.y; v[4 * q + 2] = tv.z; v[4 * q + 3] = tv.w;
    }
    float ps = 0.f, pd = 0.f;
    __half2* xo = (__half2*)(g_xh + (size_t)n * 32);
    #pragma unroll
    for (int k = 0; k < 20; k += 2) {
        ps += v[k] * s_va1[k] + v[k + 1] * s_va1[k + 1];
        pd += v[k] * s_vd1[k] + v[k + 1] * s_vd1[k + 1];
        xo[k >> 1] = __floats2half2_rn(v[k], v[k + 1]);
    }
    g_as[n] = ps; g_ad[n] = pd;
}

// ---------------- one-pass bucket scatter (replaces hist+scan+scatter) ----------
__global__ void k_scatter(const void* __restrict__ ei) {
    int q = blockIdx.x * blockDim.x + threadIdx.x;   // quad of edges
    if (q >= NE / 4) return;
    int s[4], d[4];
    if (g_is64) {
        const longlong2* ps = (const longlong2*)ei;
        const longlong2* pd = (const longlong2*)((const long long*)ei + NE);
        longlong2 a = ps[2 * q], b = ps[2 * q + 1];
        longlong2 c = pd[2 * q], f = pd[2 * q + 1];
        s[0] = (int)a.x; s[1] = (int)a.y; s[2] = (int)b.x; s[3] = (int)b.y;
        d[0] = (int)c.x; d[1] = (int)c.y; d[2] = (int)f.x; d[3] = (int)f.y;
    } else {
        int4 a = ((const int4*)ei)[q];
        int4 f = ((const int4*)((const int*)ei + NE))[q];
        s[0] = a.x; s[1] = a.y; s[2] = a.z; s[3] = a.w;
        d[0] = f.x; d[1] = f.y; d[2] = f.z; d[3] = f.w;
    }
    #pragma unroll
    for (int i = 0; i < 4; i++) {
        if ((unsigned)d[i] < NN && (unsigned)s[i] < NN) {
            int p = atomicAdd(&g_cnt[d[i]], 1);
            if (p < SLOTS) {
                g_slots[(size_t)d[i] * SLOTS + p] = s[i];
            } else {                           // never hit at this degree dist
                int sp = atomicAdd(&g_spillcnt, 1);
                if (sp < SPILLMAX) { g_spill_s[sp] = s[i]; g_spill_d[sp] = d[i]; }
            }
        }
    }
}

// ---------------- layer 1: softmax-agg x (fp16), fused W1 GEMV, fused proj2 --------
__global__ void __launch_bounds__(256)
k_agg1(const float* __restrict__ W1, const float* __restrict__ b1) {
    __shared__ float  s_W1[20 * 64];
    __shared__ float2 s_ew[8][SLOTS];    // (src as int-bits, exp weight)
    for (int i = threadIdx.x; i < 20 * 64; i += 256) s_W1[i] = W1[i];
    __syncthreads();

    int w = (blockIdx.x * 256 + threadIdx.x) >> 5;    // grid exact: NN/8 warps
    int lane = threadIdx.x & 31;
    int wl = threadIdx.x >> 5;
    int deg = g_cnt[w];
    int nm = deg < SLOTS ? deg : SLOTS;
    float adi = g_ad[w];
    const int* slot = g_slots + (size_t)w * SLOTS;

    // self loop (warp-uniform)
    float swg = __expf(lrelu(g_as[w] + adi));

    // phase A: lane-parallel weights into smem + partial denominator
    float denom = (lane == 0) ? swg : 0.f;
    for (int j = lane; j < nm; j += 32) {
        int s = slot[j];
        float wg = __expf(lrelu(g_as[s] + adi));
        s_ew[wl][j] = make_float2(__int_as_float(s), wg);
        denom += wg;
    }
    for (int o = 16; o; o >>= 1) denom += __shfl_xor_sync(0xffffffffu, denom, o);
    __syncwarp();

    // phase B: uniform edge loop, unroll 4; lanes 0..19 gather padded x rows
    const __half* xh = g_xh;
    float acc = (lane < 20) ? swg * __half2float(xh[(size_t)w * 32 + lane]) : 0.f;
    int j = 0;
    for (; j + 4 <= nm; j += 4) {
        float2 e0 = s_ew[wl][j],     e1 = s_ew[wl][j + 1];
        float2 e2 = s_ew[wl][j + 2], e3 = s_ew[wl][j + 3];
        if (lane < 20) {
            float h0 = __half2float(xh[(size_t)__float_as_int(e0.x) * 32 + lane]);
            float h1 = __half2float(xh[(size_t)__float_as_int(e1.x) * 32 + lane]);
            float h2 = __half2float(xh[(size_t)__float_as_int(e2.x) * 32 + lane]);
            float h3 = __half2float(xh[(size_t)__float_as_int(e3.x) * 32 + lane]);
            acc += e0.y * h0 + e1.y * h1 + e2.y * h2 + e3.y * h3;
        }
    }
    for (; j < nm; j++) {
        float2 e0 = s_ew[wl][j];
        if (lane < 20) acc += e0.y * __half2float(xh[(size_t)__float_as_int(e0.x) * 32 + lane]);
    }
    // spill edges (empty in practice; correct for any input)
    int sc = g_spillcnt;
    for (int i = 0; i < sc; i++) {
        if (g_spill_d[i] == w) {
            int s = g_spill_s[i];
            float wg = __expf(lrelu(g_as[s] + adi));
            denom += wg;                 // uniform across warp: consistent
            if (lane < 20) acc += wg * __half2float(xh[(size_t)s * 32 + lane]);
        }
    }
    acc *= (1.f / denom);

    // fused GEMV: out[c] = sum_k acc_k * W1[k][c]; lane owns cols 2l, 2l+1
    float o0 = 0.f, o1 = 0.f;
    #pragma unroll
    for (int k = 0; k < 20; k++) {
        float xk = __shfl_sync(0xffffffffu, acc, k);
        float2 wv = ((const float2*)(s_W1 + k * 64))[lane];
        o0 += xk * wv.x;
        o1 += xk * wv.y;
    }
    float2 bv = ((const float2*)b1)[lane];
    o0 = fmaxf(o0 + bv.x, 0.f);
    o1 = fmaxf(o1 + bv.y, 0.f);
    ((__half2*)g_fh)[(size_t)w * 32 + lane] = __floats2half2_rn(o0, o1);

    // fused layer-2 logit projections (fp32 pre-rounding values)
    float2 va = ((const float2*)g_va2)[lane];
    float2 vd = ((const float2*)g_vd2)[lane];
    float ps = o0 * va.x + o1 * va.y;
    float pd = o0 * vd.x + o1 * vd.y;
    for (int o = 16; o; o >>= 1) {
        ps += __shfl_xor_sync(0xffffffffu, ps, o);
        pd += __shfl_xor_sync(0xffffffffu, pd, o);
    }
    if (lane == 0) { g_as2[w] = ps; g_ad2[w] = pd; }
}

// ---------------- layer 2: softmax-agg feat (fp16) + fused mean + fused final -------
__global__ void __launch_bounds__(256)
k_agg2(const float* __restrict__ W2, const float* __restrict__ b2,
       float* __restrict__ out) {
    __shared__ float2 s_ew[8][SLOTS];
    __shared__ float  s_red[8][64];
    __shared__ int    s_last;
    int lane = threadIdx.x & 31;
    int wl = threadIdx.x >> 5;
    int gw = (blockIdx.x * 256 + threadIdx.x) >> 5;
    int nwarps = AGG2_GRID * 8;
    const __half2* fh = (const __half2*)g_fh;
    int sc = g_spillcnt;

    float tx = 0.f, ty = 0.f;            // persistent column totals (cols 2l, 2l+1)
    for (int w = gw; w < NN; w += nwarps) {
        int deg = g_cnt[w];
        int nm = deg < SLOTS ? deg : SLOTS;
        float adi = g_ad2[w];
        const int* slot = g_slots + (size_t)w * SLOTS;

        float swg = __expf(lrelu(g_as2[w] + adi));

        float denom = (lane == 0) ? swg : 0.f;
        for (int j = lane; j < nm; j += 32) {
            int s = slot[j];
            float wg = __expf(lrelu(g_as2[s] + adi));
            s_ew[wl][j] = make_float2(__int_as_float(s), wg);
            denom += wg;
        }
        for (int o = 16; o; o >>= 1) denom += __shfl_xor_sync(0xffffffffu, denom, o);
        __syncwarp();

        float2 hs = __half22float2(fh[(size_t)w * 32 + lane]);
        float ax = swg * hs.x, ay = swg * hs.y;
        int j = 0;
        for (; j + 4 <= nm; j += 4) {
            float2 e0 = s_ew[wl][j],     e1 = s_ew[wl][j + 1];
            float2 e2 = s_ew[wl][j + 2], e3 = s_ew[wl][j + 3];
            float2 h0 = __half22float2(fh[(size_t)__float_as_int(e0.x) * 32 + lane]);
            float2 h1 = __half22float2(fh[(size_t)__float_as_int(e1.x) * 32 + lane]);
            float2 h2 = __half22float2(fh[(size_t)__float_as_int(e2.x) * 32 + lane]);
            float2 h3 = __half22float2(fh[(size_t)__float_as_int(e3.x) * 32 + lane]);
            ax += e0.y * h0.x + e1.y * h1.x + e2.y * h2.x + e3.y * h3.x;
            ay += e0.y * h0.y + e1.y * h1.y + e2.y * h2.y + e3.y * h3.y;
        }
        for (; j < nm; j++) {
            float2 e0 = s_ew[wl][j];
            float2 h0 = __half22float2(fh[(size_t)__float_as_int(e0.x) * 32 + lane]);
            ax += e0.y * h0.x;
            ay += e0.y * h0.y;
        }
        for (int i = 0; i < sc; i++) {   // spill edges (empty in practice)
            if (g_spill_d[i] == w) {
                int s = g_spill_s[i];
                float wg = __expf(lrelu(g_as2[s] + adi));
                denom += wg;
                float2 h0 = __half22float2(fh[(size_t)s * 32 + lane]);
                ax += wg * h0.x;
                ay += wg * h0.y;
            }
        }
        float inv = 1.f / denom;
        tx += ax * inv;
        ty += ay * inv;
        __syncwarp();
    }
    s_red[wl][2 * lane] = tx;
    s_red[wl][2 * lane + 1] = ty;
    __syncthreads();
    if (threadIdx.x < 64) {
        float t = 0.f;
        #pragma unroll
        for (int i = 0; i < 8; i++) t += s_red[i][threadIdx.x];
        atomicAdd(&g_csum[threadIdx.x * 32], t);   // 128B stride -> spread LTS
        __threadfence();
    }
    __syncthreads();
    if (threadIdx.x == 0)
        s_last = (atomicAdd(&g_done, 1) == AGG2_GRID - 1);
    __syncthreads();
    if (s_last) {                        // last block: out = colmean @ W2 + b2
        __shared__ float m[64];
        int t = threadIdx.x;
        if (t < 64) m[t] = g_csum[t * 32] * (1.0f / NN);
        __syncthreads();
        if (t < 64) {
            float s = b2[t];
            for (int k = 0; k < 64; k++) s += m[k] * W2[k * 64 + t];
            out[t] = s;
        }
    }
}

// ---------------- launch ----------------
extern "C" void kernel_launch(void* const* d_in, const int* in_sizes, int n_in,
                              void* d_out, int out_size) {
    const float* x   = (const float*)d_in[0];
    const void*  ei  = d_in[1];
    const float* W1  = (const float*)d_in[2];
    const float* as1 = (const float*)d_in[3];
    const float* ad1 = (const float*)d_in[4];
    const float* b1  = (const float*)d_in[5];
    const float* W2  = (const float*)d_in[6];
    const float* as2 = (const float*)d_in[7];
    const float* ad2 = (const float*)d_in[8];
    const float* b2  = (const float*)d_in[9];
    float* out = (float*)d_out;

    int gN = (NN + 255) / 256;           // 391
    int gQ = (NE / 4 + 255) / 256;       // 977 (quad-edge)
    int gW = NN / 8;                     // 12500 (warp-per-node)

    k_init_prep<<<gN, 256>>>(x, (const int*)ei, W1, as1, ad1, W2, as2, ad2);
    k_scatter<<<gQ, 256>>>(ei);
    k_agg1<<<gW, 256>>>(W1, b1);
    k_agg2<<<AGG2_GRID, 256>>>(W2, b2, out);
}

// round 13
// speedup vs baseline: 1.2394x; 1.1163x over previous
#include <cuda_runtime.h>
#include <cuda_fp16.h>

#define NN 100000
#define NE 1000000
#define SLOTS 64              // fixed bucket slots per node (Poisson(10): max deg ~30)
#define SPILLMAX 4096
#define AGG2_GRID 888         // persistent: 148 SMs x 6 blocks

// ---------------- scratch (static device globals; no allocation) ----------------
__device__ __half g_xh[NN * 32];     // x in fp16, rows padded to 32 halves (64B)
__device__ __half g_fh[NN * 64];     // layer1 output in fp16 (128B rows)
__device__ float  g_as[NN], g_ad[NN];    // layer1 logit projections
__device__ float  g_as2[NN], g_ad2[NN];  // layer2 logit projections
__device__ int    g_cnt[NN];         // in-degree (bucket fill count)
__device__ int    g_slots[NN * SLOTS];   // src ids, bucketed by dst (256B rows)
__device__ int    g_spill_s[SPILLMAX], g_spill_d[SPILLMAX];
__device__ int    g_spillcnt;
__device__ int    g_is64;
__device__ int    g_done;
__device__ float  g_va2[64], g_vd2[64];  // W2 @ a_src2 / a_dst2
__device__ float  g_csum[64 * 32];       // padded column sums (128B stride)

__device__ __forceinline__ float lrelu(float e) { return (e > 0.f) ? e : 0.2f * e; }

// ---------------- fused init + prep ----------------
__global__ void __launch_bounds__(256)
k_init_prep(const float* __restrict__ x, const int* __restrict__ e,
            const float* __restrict__ W1, const float* __restrict__ as1,
            const float* __restrict__ ad1,
            const float* __restrict__ W2, const float* __restrict__ as2,
            const float* __restrict__ ad2) {
    __shared__ float s_va1[20], s_vd1[20];
    int t = threadIdx.x;
    int n = blockIdx.x * 256 + t;
    if (n < NN) g_cnt[n] = 0;
    if (n < 64 * 32) g_csum[n] = 0.f;
    if (n == 0) { g_done = 0; g_spillcnt = 0; }
    if (t < 20) {
        float s = 0.f;
        for (int c = 0; c < 64; c++) s += W1[t * 64 + c] * as1[c];
        s_va1[t] = s;
    } else if (t < 40) {
        int k = t - 20; float s = 0.f;
        for (int c = 0; c < 64; c++) s += W1[k * 64 + c] * ad1[c];
        s_vd1[k] = s;
    }
    if (blockIdx.x == 0) {
        if (t == 64) {
            int allz = 1;                    // int64: odd words are zero high halves
            for (int j = 1; j < 64; j += 2)
                if (e[j] != 0) allz = 0;
            g_is64 = allz;
        }
        if (t >= 128 && t < 192) {
            int k = t - 128; float s = 0.f;
            for (int c = 0; c < 64; c++) s += W2[k * 64 + c] * as2[c];
            g_va2[k] = s;
        } else if (t >= 192) {
            int k = t - 192; float s = 0.f;
            for (int c = 0; c < 64; c++) s += W2[k * 64 + c] * ad2[c];
            g_vd2[k] = s;
        }
    }
    __syncthreads();
    if (n >= NN) return;
    const float4* r4 = (const float4*)(x + (size_t)n * 20);
    float v[20];
    #pragma unroll
    for (int q = 0; q < 5; q++) {
        float4 tv = r4[q];
        v[4 * q] = tv.x; v[4 * q + 1] = tv.y; v[4 * q + 2] = tv.z; v[4 * q + 3] = tv.w;
    }
    float ps = 0.f, pd = 0.f;
    __half2* xo = (__half2*)(g_xh + (size_t)n * 32);
    #pragma unroll
    for (int k = 0; k < 20; k += 2) {
        ps += v[k] * s_va1[k] + v[k + 1] * s_va1[k + 1];
        pd += v[k] * s_vd1[k] + v[k + 1] * s_vd1[k + 1];
        xo[k >> 1] = __floats2half2_rn(v[k], v[k + 1]);
    }
    #pragma unroll
    for (int k = 10; k < 16; k++) xo[k] = __floats2half2_rn(0.f, 0.f);  // zero pad
    g_as[n] = ps; g_ad[n] = pd;
}

// ---------------- one-pass bucket scatter ----------------
__global__ void k_scatter(const void* __restrict__ ei) {
    int q = blockIdx.x * blockDim.x + threadIdx.x;   // quad of edges
    if (q >= NE / 4) return;
    int s[4], d[4];
    if (g_is64) {
        const longlong2* ps = (const longlong2*)ei;
        const longlong2* pd = (const longlong2*)((const long long*)ei + NE);
        longlong2 a = ps[2 * q], b = ps[2 * q + 1];
        longlong2 c = pd[2 * q], f = pd[2 * q + 1];
        s[0] = (int)a.x; s[1] = (int)a.y; s[2] = (int)b.x; s[3] = (int)b.y;
        d[0] = (int)c.x; d[1] = (int)c.y; d[2] = (int)f.x; d[3] = (int)f.y;
    } else {
        int4 a = ((const int4*)ei)[q];
        int4 f = ((const int4*)((const int*)ei + NE))[q];
        s[0] = a.x; s[1] = a.y; s[2] = a.z; s[3] = a.w;
        d[0] = f.x; d[1] = f.y; d[2] = f.z; d[3] = f.w;
    }
    #pragma unroll
    for (int i = 0; i < 4; i++) {
        if ((unsigned)d[i] < NN && (unsigned)s[i] < NN) {
            int p = atomicAdd(&g_cnt[d[i]], 1);
            if (p < SLOTS) {
                g_slots[(size_t)d[i] * SLOTS + p] = s[i];
            } else {                           // never hit at this degree dist
                int sp = atomicAdd(&g_spillcnt, 1);
                if (sp < SPILLMAX) { g_spill_s[sp] = s[i]; g_spill_d[sp] = d[i]; }
            }
        }
    }
}

// ---------------- layer 1: softmax-agg x (fp16), fused W1 GEMV, fused proj2 --------
// Phase B: 8 groups x 4 lanes; lane loads float4 (8 halves) -> 8 edges/iteration.
__global__ void __launch_bounds__(256)
k_agg1(const float* __restrict__ W1, const float* __restrict__ b1) {
    __shared__ float  s_W1[20 * 64];
    __shared__ float2 s_ew[8][SLOTS];    // (src as int-bits, exp weight)
    for (int i = threadIdx.x; i < 20 * 64; i += 256) s_W1[i] = W1[i];
    __syncthreads();

    int w = (blockIdx.x * 256 + threadIdx.x) >> 5;    // grid exact: NN/8 warps
    int lane = threadIdx.x & 31;
    int wl = threadIdx.x >> 5;
    int deg = g_cnt[w];
    int nm = deg < SLOTS ? deg : SLOTS;
    float adi = g_ad[w];
    const int* slot = g_slots + (size_t)w * SLOTS;
    int sc = g_spillcnt;

    float swg = __expf(lrelu(g_as[w] + adi));     // self loop (warp-uniform)

    // phase A: lane-parallel weights into smem + denominator (incl. self + spill)
    float denom = (lane == 0) ? swg : 0.f;
    for (int j = lane; j < nm; j += 32) {
        int s = slot[j];
        float wg = __expf(lrelu(g_as[s] + adi));
        s_ew[wl][j] = make_float2(__int_as_float(s), wg);
        denom += wg;
    }
    for (int i = 0; i < sc; i++)
        if (g_spill_d[i] == w && lane == 0)
            denom += __expf(lrelu(g_as[g_spill_s[i]] + adi));
    for (int o = 16; o; o >>= 1) denom += __shfl_xor_sync(0xffffffffu, denom, o);
    float inv = 1.f / denom;
    int selfIn = (nm < SLOTS);
    if (selfIn && lane == 0) s_ew[wl][nm] = make_float2(__int_as_float(w), swg);
    int nm2 = nm + selfIn;
    __syncwarp();

    // phase B: grouped gathers, pre-normalized accumulate
    int g = lane >> 2, lc = lane & 3;
    float acc[8];
    #pragma unroll
    for (int k = 0; k < 8; k++) acc[k] = 0.f;
    const char* xb = (const char*)g_xh;
    for (int j = g; j < nm2; j += 8) {
        float2 ew = s_ew[wl][j];
        int s = __float_as_int(ew.x);
        float wg = ew.y * inv;
        float4 hv = *(const float4*)(xb + s * 64 + lc * 16);
        const __half2* hp = (const __half2*)&hv;
        float2 f0 = __half22float2(hp[0]), f1 = __half22float2(hp[1]);
        float2 f2 = __half22float2(hp[2]), f3 = __half22float2(hp[3]);
        acc[0] += wg * f0.x; acc[1] += wg * f0.y;
        acc[2] += wg * f1.x; acc[3] += wg * f1.y;
        acc[4] += wg * f2.x; acc[5] += wg * f2.y;
        acc[6] += wg * f3.x; acc[7] += wg * f3.y;
    }
    if (!selfIn && g == 0) {                     // rare: self loop via group 0
        float wg = swg * inv;
        float4 hv = *(const float4*)(xb + w * 64 + lc * 16);
        const __half2* hp = (const __half2*)&hv;
        float2 f0 = __half22float2(hp[0]), f1 = __half22float2(hp[1]);
        float2 f2 = __half22float2(hp[2]), f3 = __half22float2(hp[3]);
        acc[0] += wg * f0.x; acc[1] += wg * f0.y;
        acc[2] += wg * f1.x; acc[3] += wg * f1.y;
        acc[4] += wg * f2.x; acc[5] += wg * f2.y;
        acc[6] += wg * f3.x; acc[7] += wg * f3.y;
    }
    for (int i = 0; i < sc; i++) {               // rare: spill edges via group 0
        if (g_spill_d[i] == w) {
            int s = g_spill_s[i];
            float wg = __expf(lrelu(g_as[s] + adi)) * inv;
            if (g == 0) {
                float4 hv = *(const float4*)(xb + s * 64 + lc * 16);
                const __half2* hp = (const __half2*)&hv;
                float2 f0 = __half22float2(hp[0]), f1 = __half22float2(hp[1]);
                float2 f2 = __half22float2(hp[2]), f3 = __half22float2(hp[3]);
                acc[0] += wg * f0.x; acc[1] += wg * f0.y;
                acc[2] += wg * f1.x; acc[3] += wg * f1.y;
                acc[4] += wg * f2.x; acc[5] += wg * f2.y;
                acc[6] += wg * f3.x; acc[7] += wg * f3.y;
            }
        }
    }
    // cross-group reduction: lanes with same lc hold col sums (col = 8*lc + k)
    #pragma unroll
    for (int k = 0; k < 8; k++) {
        acc[k] += __shfl_xor_sync(0xffffffffu, acc[k], 4);
        acc[k] += __shfl_xor_sync(0xffffffffu, acc[k], 8);
        acc[k] += __shfl_xor_sync(0xffffffffu, acc[k], 16);
    }

    // fused GEMV: out[c] = sum_kk agg[kk] * W1[kk][c]; agg[kk] on lane kk>>3, reg kk&7
    float o0 = 0.f, o1 = 0.f;
    #pragma unroll
    for (int kk = 0; kk < 20; kk++) {
        float xk = __shfl_sync(0xffffffffu, acc[kk & 7], kk >> 3);
        float2 wv = ((const float2*)(s_W1 + kk * 64))[lane];
        o0 += xk * wv.x;
        o1 += xk * wv.y;
    }
    float2 bv = ((const float2*)b1)[lane];
    o0 = fmaxf(o0 + bv.x, 0.f);
    o1 = fmaxf(o1 + bv.y, 0.f);
    ((__half2*)g_fh)[(size_t)w * 32 + lane] = __floats2half2_rn(o0, o1);

    // fused layer-2 logit projections
    float2 va = ((const float2*)g_va2)[lane];
    float2 vd = ((const float2*)g_vd2)[lane];
    float ps = o0 * va.x + o1 * va.y;
    float pd = o0 * vd.x + o1 * vd.y;
    for (int o = 16; o; o >>= 1) {
        ps += __shfl_xor_sync(0xffffffffu, ps, o);
        pd += __shfl_xor_sync(0xffffffffu, pd, o);
    }
    if (lane == 0) { g_as2[w] = ps; g_ad2[w] = pd; }
}

// ---------------- layer 2: softmax-agg feat (fp16) + fused mean + fused final -------
// Phase B: 4 groups x 8 lanes; lane loads float4 (8 halves) -> 4 edges/iteration.
// Pre-normalized contributions accumulate into persistent ttot; one reduction at end.
__global__ void __launch_bounds__(256)
k_agg2(const float* __restrict__ W2, const float* __restrict__ b2,
       float* __restrict__ out) {
    __shared__ float2 s_ew[8][SLOTS];
    __shared__ float  s_red[8][64];
    __shared__ int    s_last;
    int lane = threadIdx.x & 31;
    int wl = threadIdx.x >> 5;
    int gw = (blockIdx.x * 256 + threadIdx.x) >> 5;
    int nwarps = AGG2_GRID * 8;
    int g = lane >> 3, lc = lane & 7;
    const char* fb = (const char*)g_fh;
    int sc = g_spillcnt;

    float ttot[8];                        // persistent col totals (col = 8*lc + k)
    #pragma unroll
    for (int k = 0; k < 8; k++) ttot[k] = 0.f;

    for (int w = gw; w < NN; w += nwarps) {
        int deg = g_cnt[w];
        int nm = deg < SLOTS ? deg : SLOTS;
        float adi = g_ad2[w];
        const int* slot = g_slots + (size_t)w * SLOTS;

        float swg = __expf(lrelu(g_as2[w] + adi));

        float denom = (lane == 0) ? swg : 0.f;
        for (int j = lane; j < nm; j += 32) {
            int s = slot[j];
            float wg = __expf(lrelu(g_as2[s] + adi));
            s_ew[wl][j] = make_float2(__int_as_float(s), wg);
            denom += wg;
        }
        for (int i = 0; i < sc; i++)
            if (g_spill_d[i] == w && lane == 0)
                denom += __expf(lrelu(g_as2[g_spill_s[i]] + adi));
        for (int o = 16; o; o >>= 1) denom += __shfl_xor_sync(0xffffffffu, denom, o);
        float inv = 1.f / denom;
        int selfIn = (nm < SLOTS);
        if (selfIn && lane == 0) s_ew[wl][nm] = make_float2(__int_as_float(w), swg);
        int nm2 = nm + selfIn;
        __syncwarp();

        for (int j = g; j < nm2; j += 4) {
            float2 ew = s_ew[wl][j];
            int s = __float_as_int(ew.x);
            float wg = ew.y * inv;
            float4 hv = *(const float4*)(fb + s * 128 + lc * 16);
            const __half2* hp = (const __half2*)&hv;
            float2 f0 = __half22float2(hp[0]), f1 = __half22float2(hp[1]);
            float2 f2 = __half22float2(hp[2]), f3 = __half22float2(hp[3]);
            ttot[0] += wg * f0.x; ttot[1] += wg * f0.y;
            ttot[2] += wg * f1.x; ttot[3] += wg * f1.y;
            ttot[4] += wg * f2.x; ttot[5] += wg * f2.y;
            ttot[6] += wg * f3.x; ttot[7] += wg * f3.y;
        }
        if (!selfIn && g == 0) {              // rare: self via group 0
            float wg = swg * inv;
            float4 hv = *(const float4*)(fb + w * 128 + lc * 16);
            const __half2* hp = (const __half2*)&hv;
            float2 f0 = __half22float2(hp[0]), f1 = __half22float2(hp[1]);
            float2 f2 = __half22float2(hp[2]), f3 = __half22float2(hp[3]);
            ttot[0] += wg * f0.x; ttot[1] += wg * f0.y;
            ttot[2] += wg * f1.x; ttot[3] += wg * f1.y;
            ttot[4] += wg * f2.x; ttot[5] += wg * f2.y;
            ttot[6] += wg * f3.x; ttot[7] += wg * f3.y;
        }
        for (int i = 0; i < sc; i++) {        // rare: spill via group 0
            if (g_spill_d[i] == w) {
                int s = g_spill_s[i];
                float wg = __expf(lrelu(g_as2[s] + adi)) * inv;
                if (g == 0) {
                    float4 hv = *(const float4*)(fb + s * 128 + lc * 16);
                    const __half2* hp = (const __half2*)&hv;
                    float2 f0 = __half22float2(hp[0]), f1 = __half22float2(hp[1]);
                    float2 f2 = __half22float2(hp[2]), f3 = __half22float2(hp[3]);
                    ttot[0] += wg * f0.x; ttot[1] += wg * f0.y;
                    ttot[2] += wg * f1.x; ttot[3] += wg * f1.y;
                    ttot[4] += wg * f2.x; ttot[5] += wg * f2.y;
                    ttot[6] += wg * f3.x; ttot[7] += wg * f3.y;
                }
            }
        }
        __syncwarp();
    }

    // one deferred cross-group reduction per warp
    #pragma unroll
    for (int k = 0; k < 8; k++) {
        ttot[k] += __shfl_xor_sync(0xffffffffu, ttot[k], 8);
        ttot[k] += __shfl_xor_sync(0xffffffffu, ttot[k], 16);
    }
    if (lane < 8) {
        #pragma unroll
        for (int k = 0; k < 8; k++) s_red[wl][8 * lane + k] = ttot[k];
    }
    __syncthreads();
    if (threadIdx.x < 64) {
        float t = 0.f;
        #pragma unroll
        for (int i = 0; i < 8; i++) t += s_red[i][threadIdx.x];
        atomicAdd(&g_csum[threadIdx.x * 32], t);   // 128B stride -> spread LTS
        __threadfence();
    }
    __syncthreads();
    if (threadIdx.x == 0)
        s_last = (atomicAdd(&g_done, 1) == AGG2_GRID - 1);
    __syncthreads();
    if (s_last) {                        // last block: out = colmean @ W2 + b2
        __shared__ float m[64];
        int t = threadIdx.x;
        if (t < 64) m[t] = g_csum[t * 32] * (1.0f / NN);
        __syncthreads();
        if (t < 64) {
            float s = b2[t];
            for (int k = 0; k < 64; k++) s += m[k] * W2[k * 64 + t];
            out[t] = s;
        }
    }
}

// ---------------- launch ----------------
extern "C" void kernel_launch(void* const* d_in, const int* in_sizes, int n_in,
                              void* d_out, int out_size) {
    const float* x   = (const float*)d_in[0];
    const void*  ei  = d_in[1];
    const float* W1  = (const float*)d_in[2];
    const float* as1 = (const float*)d_in[3];
    const float* ad1 = (const float*)d_in[4];
    const float* b1  = (const float*)d_in[5];
    const float* W2  = (const float*)d_in[6];
    const float* as2 = (const float*)d_in[7];
    const float* ad2 = (const float*)d_in[8];
    const float* b2  = (const float*)d_in[9];
    float* out = (float*)d_out;

    int gN = (NN + 255) / 256;           // 391
    int gQ = (NE / 4 + 255) / 256;       // 977 (quad-edge)
    int gW = NN / 8;                     // 12500 (warp-per-node)

    k_init_prep<<<gN, 256>>>(x, (const int*)ei, W1, as1, ad1, W2, as2, ad2);
    k_scatter<<<gQ, 256>>>(ei);
    k_agg1<<<gW, 256>>>(W1, b1);
    k_agg2<<<AGG2_GRID, 256>>>(W2, b2, out);
}

// round 16
// speedup vs baseline: 1.2793x; 1.0322x over previous
#include <cuda_runtime.h>
#include <cuda_fp16.h>

#define NN 100000
#define NE 1000000
#define SLOTS 64              // fixed bucket slots per node (Poisson(10): max deg ~30)
#define SPILLMAX 4096
#define AGG2_GRID 888         // persistent: 148 SMs x 6 blocks

// ---------------- scratch (static device globals; no allocation) ----------------
__device__ __half g_xh[NN * 32];     // x in fp16, rows padded to 32 halves (64B)
__device__ __half g_fh[NN * 64];     // layer1 output in fp16 (128B rows)
__device__ float  g_as[NN], g_ad[NN];    // layer1 logit projections
__device__ float  g_as2[NN], g_ad2[NN];  // layer2 logit projections
__device__ int    g_cnt[NN];         // in-degree (bucket fill count)
__device__ int    g_slots[NN * SLOTS];   // src ids, bucketed by dst (256B rows)
__device__ int    g_spill_s[SPILLMAX], g_spill_d[SPILLMAX];
__device__ int    g_spillcnt;
__device__ int    g_is64;
__device__ int    g_done;
__device__ float  g_va2[64], g_vd2[64];  // W2 @ a_src2 / a_dst2
__device__ float  g_csum[64 * 32];       // padded column sums (128B stride)

__device__ __forceinline__ float lrelu(float e) { return (e > 0.f) ? e : 0.2f * e; }

// ---------------- fused init + prep ----------------
__global__ void __launch_bounds__(256)
k_init_prep(const float* __restrict__ x, const int* __restrict__ e,
            const float* __restrict__ W1, const float* __restrict__ as1,
            const float* __restrict__ ad1,
            const float* __restrict__ W2, const float* __restrict__ as2,
            const float* __restrict__ ad2) {
    __shared__ float s_va1[20], s_vd1[20];
    int t = threadIdx.x;
    int n = blockIdx.x * 256 + t;
    if (n < NN) g_cnt[n] = 0;
    if (n < 64 * 32) g_csum[n] = 0.f;
    if (n == 0) { g_done = 0; g_spillcnt = 0; }
    if (t < 20) {
        float s = 0.f;
        for (int c = 0; c < 64; c++) s += W1[t * 64 + c] * as1[c];
        s_va1[t] = s;
    } else if (t < 40) {
        int k = t - 20; float s = 0.f;
        for (int c = 0; c < 64; c++) s += W1[k * 64 + c] * ad1[c];
        s_vd1[k] = s;
    }
    if (blockIdx.x == 0) {
        if (t == 64) {
            int allz = 1;                    // int64: odd words are zero high halves
            for (int j = 1; j < 64; j += 2)
                if (e[j] != 0) allz = 0;
            g_is64 = allz;
        }
        if (t >= 128 && t < 192) {
            int k = t - 128; float s = 0.f;
            for (int c = 0; c < 64; c++) s += W2[k * 64 + c] * as2[c];
            g_va2[k] = s;
        } else if (t >= 192) {
            int k = t - 192; float s = 0.f;
            for (int c = 0; c < 64; c++) s += W2[k * 64 + c] * ad2[c];
            g_vd2[k] = s;
        }
    }
    __syncthreads();
    if (n >= NN) return;
    const float4* r4 = (const float4*)(x + (size_t)n * 20);
    float v[20];
    #pragma unroll
    for (int q = 0; q < 5; q++) {
        float4 tv = r4[q];
        v[4 * q] = tv.x; v[4 * q + 1] = tv.y; v[4 * q + 2] = tv.z; v[4 * q + 3] = tv.w;
    }
    float ps = 0.f, pd = 0.f;
    __half2* xo = (__half2*)(g_xh + (size_t)n * 32);
    #pragma unroll
    for (int k = 0; k < 20; k += 2) {
        ps += v[k] * s_va1[k] + v[k + 1] * s_va1[k + 1];
        pd += v[k] * s_vd1[k] + v[k + 1] * s_vd1[k + 1];
        xo[k >> 1] = __floats2half2_rn(v[k], v[k + 1]);
    }
    #pragma unroll
    for (int k = 10; k < 16; k++) xo[k] = __floats2half2_rn(0.f, 0.f);  // zero pad
    g_as[n] = ps; g_ad[n] = pd;
}

// ---------------- one-pass bucket scatter ----------------
__global__ void k_scatter(const void* __restrict__ ei) {
    int q = blockIdx.x * blockDim.x + threadIdx.x;   // quad of edges
    if (q >= NE / 4) return;
    int s[4], d[4];
    if (g_is64) {
        const longlong2* ps = (const longlong2*)ei;
        const longlong2* pd = (const longlong2*)((const long long*)ei + NE);
        longlong2 a = ps[2 * q], b = ps[2 * q + 1];
        longlong2 c = pd[2 * q], f = pd[2 * q + 1];
        s[0] = (int)a.x; s[1] = (int)a.y; s[2] = (int)b.x; s[3] = (int)b.y;
        d[0] = (int)c.x; d[1] = (int)c.y; d[2] = (int)f.x; d[3] = (int)f.y;
    } else {
        int4 a = ((const int4*)ei)[q];
        int4 f = ((const int4*)((const int*)ei + NE))[q];
        s[0] = a.x; s[1] = a.y; s[2] = a.z; s[3] = a.w;
        d[0] = f.x; d[1] = f.y; d[2] = f.z; d[3] = f.w;
    }
    #pragma unroll
    for (int i = 0; i < 4; i++) {
        if ((unsigned)d[i] < NN && (unsigned)s[i] < NN) {
            int p = atomicAdd(&g_cnt[d[i]], 1);
            if (p < SLOTS) {
                g_slots[(size_t)d[i] * SLOTS + p] = s[i];
            } else {                           // never hit at this degree dist
                int sp = atomicAdd(&g_spillcnt, 1);
                if (sp < SPILLMAX) { g_spill_s[sp] = s[i]; g_spill_d[sp] = d[i]; }
            }
        }
    }
}

// ---------------- layer 1: softmax-agg x (fp16/HFMA2), fused W1 GEMV, fused proj2 --
// Phase B: 8 groups x 4 lanes; lane loads float4 (8 halves) -> 8 edges/iteration.
__global__ void __launch_bounds__(512)
k_agg1(const float* __restrict__ W1, const float* __restrict__ b1) {
    __shared__ float  s_W1[20 * 64];
    __shared__ float2 s_ew[16][SLOTS];   // (src as int-bits, exp weight)
    for (int i = threadIdx.x; i < 20 * 64; i += 512) s_W1[i] = W1[i];
    __syncthreads();

    int w = (blockIdx.x * 512 + threadIdx.x) >> 5;    // grid exact: NN/16 warps
    int lane = threadIdx.x & 31;
    int wl = threadIdx.x >> 5;
    int deg = g_cnt[w];
    int nm = deg < SLOTS ? deg : SLOTS;
    float adi = g_ad[w];
    const int* slot = g_slots + (size_t)w * SLOTS;
    int sc = g_spillcnt;

    float swg = __expf(lrelu(g_as[w] + adi));     // self loop (warp-uniform)

    // phase A: lane-parallel weights into smem + denominator (incl. self + spill)
    float denom = (lane == 0) ? swg : 0.f;
    for (int j = lane; j < nm; j += 32) {
        int s = slot[j];
        float wg = __expf(lrelu(g_as[s] + adi));
        s_ew[wl][j] = make_float2(__int_as_float(s), wg);
        denom += wg;
    }
    for (int i = 0; i < sc; i++)
        if (g_spill_d[i] == w && lane == 0)
            denom += __expf(lrelu(g_as[g_spill_s[i]] + adi));
    for (int o = 16; o; o >>= 1) denom += __shfl_xor_sync(0xffffffffu, denom, o);
    float inv = 1.f / denom;
    int selfIn = (nm < SLOTS);
    if (selfIn && lane == 0) s_ew[wl][nm] = make_float2(__int_as_float(w), swg);
    int nm2 = nm + selfIn;
    __syncwarp();

    // phase B: grouped half2 gathers, pre-normalized HFMA2 accumulate
    int g = lane >> 2, lc = lane & 3;
    __half2 acch[4];
    #pragma unroll
    for (int k = 0; k < 4; k++) acch[k] = __floats2half2_rn(0.f, 0.f);
    const char* xb = (const char*)g_xh;
    for (int j = g; j < nm2; j += 8) {
        float2 ew = s_ew[wl][j];
        int s = __float_as_int(ew.x);
        __half2 wh = __float2half2_rn(ew.y * inv);
        float4 hv = *(const float4*)(xb + s * 64 + lc * 16);
        const __half2* hp = (const __half2*)&hv;
        acch[0] = __hfma2(wh, hp[0], acch[0]);
        acch[1] = __hfma2(wh, hp[1], acch[1]);
        acch[2] = __hfma2(wh, hp[2], acch[2]);
        acch[3] = __hfma2(wh, hp[3], acch[3]);
    }
    if (!selfIn && g == 0) {                     // rare: self loop via group 0
        __half2 wh = __float2half2_rn(swg * inv);
        float4 hv = *(const float4*)(xb + w * 64 + lc * 16);
        const __half2* hp = (const __half2*)&hv;
        #pragma unroll
        for (int k = 0; k < 4; k++) acch[k] = __hfma2(wh, hp[k], acch[k]);
    }
    for (int i = 0; i < sc; i++) {               // rare: spill edges via group 0
        if (g_spill_d[i] == w) {
            int s = g_spill_s[i];
            float wgf = __expf(lrelu(g_as[s] + adi)) * inv;
            if (g == 0) {
                __half2 wh = __float2half2_rn(wgf);
                float4 hv = *(const float4*)(xb + s * 64 + lc * 16);
                const __half2* hp = (const __half2*)&hv;
                #pragma unroll
                for (int k = 0; k < 4; k++) acch[k] = __hfma2(wh, hp[k], acch[k]);
            }
        }
    }
    // to fp32, cross-group reduction: lanes w/ same lc hold col sums (col = 8lc+k)
    float acc[8];
    #pragma unroll
    for (int k = 0; k < 4; k++) {
        float2 f = __half22float2(acch[k]);
        acc[2 * k] = f.x; acc[2 * k + 1] = f.y;
    }
    #pragma unroll
    for (int k = 0; k < 8; k++) {
        acc[k] += __shfl_xor_sync(0xffffffffu, acc[k], 4);
        acc[k] += __shfl_xor_sync(0xffffffffu, acc[k], 8);
        acc[k] += __shfl_xor_sync(0xffffffffu, acc[k], 16);
    }

    // fused GEMV: out[c] = sum_kk agg[kk] * W1[kk][c]; agg[kk] on lane kk>>3, reg kk&7
    float o0 = 0.f, o1 = 0.f;
    #pragma unroll
    for (int kk = 0; kk < 20; kk++) {
        float xk = __shfl_sync(0xffffffffu, acc[kk & 7], kk >> 3);
        float2 wv = ((const float2*)(s_W1 + kk * 64))[lane];
        o0 += xk * wv.x;
        o1 += xk * wv.y;
    }
    float2 bv = ((const float2*)b1)[lane];
    o0 = fmaxf(o0 + bv.x, 0.f);
    o1 = fmaxf(o1 + bv.y, 0.f);
    ((__half2*)g_fh)[(size_t)w * 32 + lane] = __floats2half2_rn(o0, o1);

    // fused layer-2 logit projections
    float2 va = ((const float2*)g_va2)[lane];
    float2 vd = ((const float2*)g_vd2)[lane];
    float ps = o0 * va.x + o1 * va.y;
    float pd = o0 * vd.x + o1 * vd.y;
    for (int o = 16; o; o >>= 1) {
        ps += __shfl_xor_sync(0xffffffffu, ps, o);
        pd += __shfl_xor_sync(0xffffffffu, pd, o);
    }
    if (lane == 0) { g_as2[w] = ps; g_ad2[w] = pd; }
}

// ---------------- layer 2: softmax-agg feat (fp16/HFMA2) + fused mean + final ------
// Phase B: 4 groups x 8 lanes; lane loads float4 (8 halves) -> 4 edges/iteration.
// Per-node fp16 accumulators; converted to fp32 persistent totals per node.
__global__ void __launch_bounds__(256)
k_agg2(const float* __restrict__ W2, const float* __restrict__ b2,
       float* __restrict__ out) {
    __shared__ float2 s_ew[8][SLOTS];
    __shared__ float  s_red[8][64];
    __shared__ int    s_last;
    int lane = threadIdx.x & 31;
    int wl = threadIdx.x >> 5;
    int gw = (blockIdx.x * 256 + threadIdx.x) >> 5;
    int nwarps = AGG2_GRID * 8;
    int g = lane >> 3, lc = lane & 7;
    const char* fb = (const char*)g_fh;
    int sc = g_spillcnt;

    float ttot[8];                        // persistent col totals (col = 8*lc + k)
    #pragma unroll
    for (int k = 0; k < 8; k++) ttot[k] = 0.f;

    for (int w = gw; w < NN; w += nwarps) {
        int deg = g_cnt[w];
        int nm = deg < SLOTS ? deg : SLOTS;
        float adi = g_ad2[w];
        const int* slot = g_slots + (size_t)w * SLOTS;

        float swg = __expf(lrelu(g_as2[w] + adi));

        float denom = (lane == 0) ? swg : 0.f;
        for (int j = lane; j < nm; j += 32) {
            int s = slot[j];
            float wg = __expf(lrelu(g_as2[s] + adi));
            s_ew[wl][j] = make_float2(__int_as_float(s), wg);
            denom += wg;
        }
        for (int i = 0; i < sc; i++)
            if (g_spill_d[i] == w && lane == 0)
                denom += __expf(lrelu(g_as2[g_spill_s[i]] + adi));
        for (int o = 16; o; o >>= 1) denom += __shfl_xor_sync(0xffffffffu, denom, o);
        float inv = 1.f / denom;
        int selfIn = (nm < SLOTS);
        if (selfIn && lane == 0) s_ew[wl][nm] = make_float2(__int_as_float(w), swg);
        int nm2 = nm + selfIn;
        __syncwarp();

        __half2 acch[4];
        #pragma unroll
        for (int k = 0; k < 4; k++) acch[k] = __floats2half2_rn(0.f, 0.f);
        for (int j = g; j < nm2; j += 4) {
            float2 ew = s_ew[wl][j];
            int s = __float_as_int(ew.x);
            __half2 wh = __float2half2_rn(ew.y * inv);
            float4 hv = *(const float4*)(fb + s * 128 + lc * 16);
            const __half2* hp = (const __half2*)&hv;
            acch[0] = __hfma2(wh, hp[0], acch[0]);
            acch[1] = __hfma2(wh, hp[1], acch[1]);
            acch[2] = __hfma2(wh, hp[2], acch[2]);
            acch[3] = __hfma2(wh, hp[3], acch[3]);
        }
        if (!selfIn && g == 0) {              // rare: self via group 0
            __half2 wh = __float2half2_rn(swg * inv);
            float4 hv = *(const float4*)(fb + w * 128 + lc * 16);
            const __half2* hp = (const __half2*)&hv;
            #pragma unroll
            for (int k = 0; k < 4; k++) acch[k] = __hfma2(wh, hp[k], acch[k]);
        }
        for (int i = 0; i < sc; i++) {        // rare: spill via group 0
            if (g_spill_d[i] == w) {
                int s = g_spill_s[i];
                float wgf = __expf(lrelu(g_as2[s] + adi)) * inv;
                if (g == 0) {
                    __half2 wh = __float2half2_rn(wgf);
                    float4 hv = *(const float4*)(fb + s * 128 + lc * 16);
                    const __half2* hp = (const __half2*)&hv;
                    #pragma unroll
                    for (int k = 0; k < 4; k++) acch[k] = __hfma2(wh, hp[k], acch[k]);
                }
            }
        }
        #pragma unroll
        for (int k = 0; k < 4; k++) {         // node done: fold into fp32 totals
            float2 f = __half22float2(acch[k]);
            ttot[2 * k]     += f.x;
            ttot[2 * k + 1] += f.y;
        }
        __syncwarp();
    }

    // one deferred cross-group reduction per warp
    #pragma unroll
    for (int k = 0; k < 8; k++) {
        ttot[k] += __shfl_xor_sync(0xffffffffu, ttot[k], 8);
        ttot[k] += __shfl_xor_sync(0xffffffffu, ttot[k], 16);
    }
    if (lane < 8) {
        #pragma unroll
        for (int k = 0; k < 8; k++) s_red[wl][8 * lane + k] = ttot[k];
    }
    __syncthreads();
    if (threadIdx.x < 64) {
        float t = 0.f;
        #pragma unroll
        for (int i = 0; i < 8; i++) t += s_red[i][threadIdx.x];
        atomicAdd(&g_csum[threadIdx.x * 32], t);   // 128B stride -> spread LTS
        __threadfence();
    }
    __syncthreads();
    if (threadIdx.x == 0)
        s_last = (atomicAdd(&g_done, 1) == AGG2_GRID - 1);
    __syncthreads();
    if (s_last) {                        // last block: out = colmean @ W2 + b2
        __shared__ float m[64];
        int t = threadIdx.x;
        if (t < 64) m[t] = g_csum[t * 32] * (1.0f / NN);
        __syncthreads();
        if (t < 64) {
            float s = b2[t];
            for (int k = 0; k < 64; k++) s += m[k] * W2[k * 64 + t];
            out[t] = s;
        }
    }
}

// ---------------- launch ----------------
extern "C" void kernel_launch(void* const* d_in, const int* in_sizes, int n_in,
                              void* d_out, int out_size) {
    const float* x   = (const float*)d_in[0];
    const void*  ei  = d_in[1];
    const float* W1  = (const float*)d_in[2];
    const float* as1 = (const float*)d_in[3];
    const float* ad1 = (const float*)d_in[4];
    const float* b1  = (const float*)d_in[5];
    const float* W2  = (const float*)d_in[6];
    const float* as2 = (const float*)d_in[7];
    const float* ad2 = (const float*)d_in[8];
    const float* b2  = (const float*)d_in[9];
    float* out = (float*)d_out;

    int gN = (NN + 255) / 256;           // 391
    int gQ = (NE / 4 + 255) / 256;       // 977 (quad-edge)
    int gW = NN / 16;                    // 6250 (warp-per-node, 512-thread blocks)

    k_init_prep<<<gN, 256>>>(x, (const int*)ei, W1, as1, ad1, W2, as2, ad2);
    k_scatter<<<gQ, 256>>>(ei);
    k_agg1<<<gW, 512>>>(W1, b1);
    k_agg2<<<AGG2_GRID, 256>>>(W2, b2, out);
}